// round 4
// baseline (speedup 1.0000x reference)
#include <cuda_runtime.h>
#include <cuda_bf16.h>

#define N_PART 1000000
#define N_GRID 128
#define N_NODES (N_GRID * N_GRID)
#define NREP 16

// Grid scratch (device globals — no allocation allowed)
__device__ __align__(16) float2 g_mom[NREP][N_NODES];   // folded momentum
__device__ float g_mass[NREP][N_NODES];                 // mass
__device__ float2 g_gv[N_NODES];                        // final grid velocity

__global__ void k_zero() {
    int n = blockIdx.x * blockDim.x + threadIdx.x;
    if (n < N_NODES * NREP) {
        ((float2*)g_mom)[n] = make_float2(0.f, 0.f);
        ((float*)g_mass)[n] = 0.f;
    }
}

__global__ void __launch_bounds__(256) k_p2g(
    const float2* __restrict__ x, const float2* __restrict__ v,
    const float4* __restrict__ C, const float4* __restrict__ F,
    const int* __restrict__ material, const float* __restrict__ Jp,
    float* __restrict__ out)
{
    int p = blockIdx.x * blockDim.x + threadIdx.x;
    if (p >= N_PART) return;
    int r = blockIdx.x & (NREP - 1);
    float2* __restrict__ rep_mom = g_mom[r];
    float* __restrict__ rep_mass = g_mass[r];

    const float DT = 1e-4f;
    const float INV_DX = 128.0f;
    const float DX = 1.0f / 128.0f;
    const float P_MASS = 1.52587890625e-05f;     // (DX*0.5)^2 * 1.0
    const float MU_0 = 1000.0f / (2.0f * 1.2f);  // 416.6667
    const float LAM_0 = 1000.0f * 0.2f / (1.2f * 0.6f); // 277.7778

    float2 xp = x[p];
    float2 vp = v[p];
    float4 c = C[p];
    float4 f = F[p];
    int m = material[p];
    float jp = Jp[p];

    // F = F + DT * (C @ F)
    float f00 = f.x + DT * (c.x * f.x + c.y * f.z);
    float f01 = f.y + DT * (c.x * f.y + c.y * f.w);
    float f10 = f.z + DT * (c.z * f.x + c.w * f.z);
    float f11 = f.w + DT * (c.z * f.y + c.w * f.w);

    float h = (m == 1) ? 0.3f : expf(10.0f * (1.0f - jp));
    float mu = (m == 0) ? 0.0f : MU_0 * h;
    float lam = LAM_0 * h;

    // Closed-form 2x2 SVD: F = R(phi) * diag(sx, sy) * R(theta)
    float E  = 0.5f * (f00 + f11);
    float Fm = 0.5f * (f00 - f11);
    float G  = 0.5f * (f10 + f01);
    float H  = 0.5f * (f10 - f01);
    float Q  = sqrtf(E * E + H * H);
    float Rr = sqrtf(Fm * Fm + G * G);
    float sx = Q + Rr;
    float sy = Q - Rr;
    float a1 = atan2f(G, Fm);
    float a2 = atan2f(H, E);
    float th = 0.5f * (a2 - a1);
    float ph = 0.5f * (a2 + a1);
    float st, ct, sp, cp;
    sincosf(th, &st, &ct);
    sincosf(ph, &sp, &cp);

    // clamp & Jp update (material 2 only)
    float clx = fminf(fmaxf(sx, 0.975f), 1.0045f);
    float cly = fminf(fmaxf(sy, 0.975f), 1.0045f);
    if (m == 2) jp *= (sx / clx) * (sy / cly);
    float s0 = (m == 2) ? clx : sx;
    float s1 = (m == 2) ? cly : sy;
    float J = s0 * s1;

    if (m == 0) {
        float sj = sqrtf(J);
        f00 = sj; f01 = 0.f; f10 = 0.f; f11 = sj;
    } else if (m == 2) {
        // F = R(phi) diag(s0,s1) R(theta)
        f00 =  cp * s0 * ct - sp * s1 * st;
        f01 = -cp * s0 * st - sp * s1 * ct;
        f10 =  sp * s0 * ct + cp * s1 * st;
        f11 = -sp * s0 * st + cp * s1 * ct;
    }

    // R = R(phi + theta)
    float crr = cp * ct - sp * st;
    float srr = sp * ct + cp * st;
    float r00 = crr, r01 = -srr, r10 = srr, r11 = crr;

    // stress = -DT * (2*mu*(F-R)@F^T + I*lam*J*(J-1))   [P_VOL*4*INV_DX^2 == 1]
    float d00 = f00 - r00, d01 = f01 - r01;
    float d10 = f10 - r10, d11 = f11 - r11;
    float tm = 2.0f * mu;
    float diag = lam * J * (J - 1.0f);
    float s00 = tm * (d00 * f00 + d01 * f01) + diag;
    float s01 = tm * (d00 * f10 + d01 * f11);
    float s10 = tm * (d10 * f00 + d11 * f01);
    float s11 = tm * (d10 * f10 + d11 * f11) + diag;
    const float scale = -1e-4f;  // -DT
    float a00 = scale * s00 + P_MASS * c.x;
    float a01 = scale * s01 + P_MASS * c.y;
    float a10 = scale * s10 + P_MASS * c.z;
    float a11 = scale * s11 + P_MASS * c.w;

    float momx = P_MASS * vp.x - (a00 * xp.x + a01 * xp.y);
    float momy = P_MASS * vp.y - (a10 * xp.x + a11 * xp.y);

    float bxf = floorf(xp.x * INV_DX - 0.5f);
    float byf = floorf(xp.y * INV_DX - 0.5f);
    int bx = (int)bxf, by = (int)byf;
    float fxx = xp.x * INV_DX - bxf;
    float fxy = xp.y * INV_DX - byf;
    float wx[3], wy[3];
    wx[0] = 0.5f * (1.5f - fxx) * (1.5f - fxx);
    wx[1] = 0.75f - (fxx - 1.0f) * (fxx - 1.0f);
    wx[2] = 0.5f * (fxx - 0.5f) * (fxx - 0.5f);
    wy[0] = 0.5f * (1.5f - fxy) * (1.5f - fxy);
    wy[1] = 0.75f - (fxy - 1.0f) * (fxy - 1.0f);
    wy[2] = 0.5f * (fxy - 0.5f) * (fxy - 0.5f);

    // Fold the affine contribution (grid_aff @ node_pos) into the scattered
    // momentum: contrib = wt * (mom + A @ node_pos).
    // RED.64 (momentum) + RED.32 (mass) per node -> 3 atomic lanes, no pad.
    #pragma unroll
    for (int i = 0; i < 3; i++) {
        float nodex = (float)(bx + i) * DX;
        float axx = a00 * nodex;   // partial A@node for this column
        float ayx = a10 * nodex;
        #pragma unroll
        for (int j = 0; j < 3; j++) {
            float nodey = (float)(by + j) * DX;
            float wt = wx[i] * wy[j];
            int idx = (bx + i) * N_GRID + (by + j);
            float cx = wt * (momx + axx + a01 * nodey);
            float cy = wt * (momy + ayx + a11 * nodey);
            atomicAdd(&rep_mom[idx], make_float2(cx, cy));
            atomicAdd(&rep_mass[idx], wt * P_MASS);
        }
    }

    // Outputs: F at 8M, material at 12M, Jp at 13M
    ((float4*)(out + 8000000))[p] = make_float4(f00, f01, f10, f11);
    out[12000000 + p] = (float)m;
    out[13000000 + p] = jp;
}

__global__ void k_grid() {
    int n = blockIdx.x * blockDim.x + threadIdx.x;
    if (n >= N_NODES) return;
    int i = n >> 7;
    int j = n & 127;
    const float DT = 1e-4f;

    float vx = 0.f, vy = 0.f, mm = 0.f;
    #pragma unroll
    for (int r = 0; r < NREP; r++) {
        float2 nd = g_mom[r][n];
        vx += nd.x; vy += nd.y;
        mm += g_mass[r][n];
    }
    if (mm > 0.0f) {
        vx /= mm;
        vy /= mm;
        vy += -DT * 50.0f;
    }
    if (i < 3)    vx = fmaxf(vx, 0.0f);
    if (i >= 126) vx = fminf(vx, 0.0f);
    if (j < 3)    vy = fmaxf(vy, 0.0f);
    if (j >= 126) vy = fminf(vy, 0.0f);
    g_gv[n] = make_float2(vx, vy);
}

__global__ void __launch_bounds__(256) k_g2p(
    const float2* __restrict__ x, float* __restrict__ out)
{
    int p = blockIdx.x * blockDim.x + threadIdx.x;
    if (p >= N_PART) return;

    const float DT = 1e-4f;
    const float INV_DX = 128.0f;
    const float DX = 1.0f / 128.0f;

    float2 xp = x[p];
    float bxf = floorf(xp.x * INV_DX - 0.5f);
    float byf = floorf(xp.y * INV_DX - 0.5f);
    int bx = (int)bxf, by = (int)byf;
    float fxx = xp.x * INV_DX - bxf;
    float fxy = xp.y * INV_DX - byf;
    float wx[3], wy[3];
    wx[0] = 0.5f * (1.5f - fxx) * (1.5f - fxx);
    wx[1] = 0.75f - (fxx - 1.0f) * (fxx - 1.0f);
    wx[2] = 0.5f * (fxx - 0.5f) * (fxx - 0.5f);
    wy[0] = 0.5f * (1.5f - fxy) * (1.5f - fxy);
    wy[1] = 0.75f - (fxy - 1.0f) * (fxy - 1.0f);
    wy[2] = 0.5f * (fxy - 0.5f) * (fxy - 0.5f);

    float nvx = 0.f, nvy = 0.f;
    float b00 = 0.f, b01 = 0.f, b10 = 0.f, b11 = 0.f;

    #pragma unroll
    for (int i = 0; i < 3; i++) {
        float nodex = (float)(bx + i) * DX;
        #pragma unroll
        for (int j = 0; j < 3; j++) {
            float wt = wx[i] * wy[j];
            int idx = (bx + i) * N_GRID + (by + j);
            float2 gv = g_gv[idx];
            float nodey = (float)(by + j) * DX;
            nvx += wt * gv.x;
            nvy += wt * gv.y;
            b00 += wt * gv.x * nodex;
            b01 += wt * gv.x * nodey;
            b10 += wt * gv.y * nodex;
            b11 += wt * gv.y * nodey;
        }
    }

    const float k4 = 65536.0f;  // 4 * INV_DX^2
    float C00 = (b00 - nvx * xp.x) * k4;
    float C01 = (b01 - nvx * xp.y) * k4;
    float C10 = (b10 - nvy * xp.x) * k4;
    float C11 = (b11 - nvy * xp.y) * k4;

    ((float2*)out)[p] = make_float2(xp.x + DT * nvx, xp.y + DT * nvy);
    ((float2*)(out + 2000000))[p] = make_float2(nvx, nvy);
    ((float4*)(out + 4000000))[p] = make_float4(C00, C01, C10, C11);
}

extern "C" void kernel_launch(void* const* d_in, const int* in_sizes, int n_in,
                              void* d_out, int out_size) {
    const float2* x  = (const float2*)d_in[0];
    const float2* v  = (const float2*)d_in[1];
    const float4* C  = (const float4*)d_in[2];
    const float4* F  = (const float4*)d_in[3];
    const int* mat   = (const int*)d_in[4];
    const float* Jp  = (const float*)d_in[5];
    float* out = (float*)d_out;

    k_zero<<<(N_NODES * NREP + 255) / 256, 256>>>();
    k_p2g<<<(N_PART + 255) / 256, 256>>>(x, v, C, F, mat, Jp, out);
    k_grid<<<(N_NODES + 255) / 256, 256>>>();
    k_g2p<<<(N_PART + 255) / 256, 256>>>(x, out);
}

// round 5
// speedup vs baseline: 1.1391x; 1.1391x over previous
#include <cuda_runtime.h>
#include <cuda_bf16.h>

#define N_PART 1000000
#define N_GRID 128
#define N_NODES (N_GRID * N_GRID)

// ---- device scratch (no runtime allocation allowed) ----
__device__ int g_cnt[N_NODES];            // particles per bin (by base)
__device__ int g_off[N_NODES];            // exclusive scan of counts
__device__ int g_cur[N_NODES];            // mutable cursor for slot assignment
__device__ __align__(16) float4 g_payA[N_PART];  // momx,momy,fxx,fxy
__device__ __align__(16) float4 g_payB[N_PART];  // a00,a01,a10,a11
__device__ float2 g_pmom[9][N_NODES];     // per-bin partial momentum per node-offset
__device__ float  g_pmass[9][N_NODES];    // per-bin partial mass per node-offset
__device__ float2 g_gv[N_NODES];          // final grid velocity

__global__ void k_zero_cnt() {
    int n = blockIdx.x * blockDim.x + threadIdx.x;
    if (n < N_NODES) g_cnt[n] = 0;
}

__global__ void __launch_bounds__(256) k_count(const float2* __restrict__ x) {
    int p = blockIdx.x * blockDim.x + threadIdx.x;
    if (p >= N_PART) return;
    float2 xp = x[p];
    int bx = (int)floorf(xp.x * 128.0f - 0.5f);
    int by = (int)floorf(xp.y * 128.0f - 0.5f);
    atomicAdd(&g_cnt[bx * N_GRID + by], 1);
}

__global__ void __launch_bounds__(1024) k_scan() {
    __shared__ int s[1024];
    int tid = threadIdx.x;
    int base = tid * 16;
    int loc[16];
    int sum = 0;
    #pragma unroll
    for (int k = 0; k < 16; k++) { loc[k] = g_cnt[base + k]; sum += loc[k]; }
    s[tid] = sum;
    __syncthreads();
    for (int off = 1; off < 1024; off <<= 1) {
        int v = 0;
        if (tid >= off) v = s[tid - off];
        __syncthreads();
        if (tid >= off) s[tid] += v;
        __syncthreads();
    }
    int excl = s[tid] - sum;
    #pragma unroll
    for (int k = 0; k < 16; k++) {
        g_off[base + k] = excl;
        g_cur[base + k] = excl;
        excl += loc[k];
    }
}

__global__ void __launch_bounds__(256) k_payload(
    const float2* __restrict__ x, const float2* __restrict__ v,
    const float4* __restrict__ C, const float4* __restrict__ F,
    const int* __restrict__ material, const float* __restrict__ Jp,
    float* __restrict__ out)
{
    int p = blockIdx.x * blockDim.x + threadIdx.x;
    if (p >= N_PART) return;

    const float DT = 1e-4f;
    const float INV_DX = 128.0f;
    const float P_MASS = 1.52587890625e-05f;
    const float MU_0 = 1000.0f / (2.0f * 1.2f);
    const float LAM_0 = 1000.0f * 0.2f / (1.2f * 0.6f);

    float2 xp = x[p];
    float2 vp = v[p];
    float4 c = C[p];
    float4 f = F[p];
    int m = material[p];
    float jp = Jp[p];

    // F = F + DT * (C @ F)
    float f00 = f.x + DT * (c.x * f.x + c.y * f.z);
    float f01 = f.y + DT * (c.x * f.y + c.y * f.w);
    float f10 = f.z + DT * (c.z * f.x + c.w * f.z);
    float f11 = f.w + DT * (c.z * f.y + c.w * f.w);

    float h = (m == 1) ? 0.3f : expf(10.0f * (1.0f - jp));
    float mu = (m == 0) ? 0.0f : MU_0 * h;
    float lam = LAM_0 * h;

    // Closed-form 2x2 SVD: F = R(phi) * diag(sx, sy) * R(theta)
    float E  = 0.5f * (f00 + f11);
    float Fm = 0.5f * (f00 - f11);
    float G  = 0.5f * (f10 + f01);
    float H  = 0.5f * (f10 - f01);
    float Q  = sqrtf(E * E + H * H);
    float Rr = sqrtf(Fm * Fm + G * G);
    float sx = Q + Rr;
    float sy = Q - Rr;
    float a1 = atan2f(G, Fm);
    float a2 = atan2f(H, E);
    float th = 0.5f * (a2 - a1);
    float ph = 0.5f * (a2 + a1);
    float st, ct, sp, cp;
    sincosf(th, &st, &ct);
    sincosf(ph, &sp, &cp);

    float clx = fminf(fmaxf(sx, 0.975f), 1.0045f);
    float cly = fminf(fmaxf(sy, 0.975f), 1.0045f);
    if (m == 2) jp *= (sx / clx) * (sy / cly);
    float s0 = (m == 2) ? clx : sx;
    float s1 = (m == 2) ? cly : sy;
    float J = s0 * s1;

    if (m == 0) {
        float sj = sqrtf(J);
        f00 = sj; f01 = 0.f; f10 = 0.f; f11 = sj;
    } else if (m == 2) {
        f00 =  cp * s0 * ct - sp * s1 * st;
        f01 = -cp * s0 * st - sp * s1 * ct;
        f10 =  sp * s0 * ct + cp * s1 * st;
        f11 = -sp * s0 * st + cp * s1 * ct;
    }

    float crr = cp * ct - sp * st;
    float srr = sp * ct + cp * st;
    float r00 = crr, r01 = -srr, r10 = srr, r11 = crr;

    float d00 = f00 - r00, d01 = f01 - r01;
    float d10 = f10 - r10, d11 = f11 - r11;
    float tm = 2.0f * mu;
    float diag = lam * J * (J - 1.0f);
    float s00 = tm * (d00 * f00 + d01 * f01) + diag;
    float s01 = tm * (d00 * f10 + d01 * f11);
    float s10 = tm * (d10 * f00 + d11 * f01);
    float s11 = tm * (d10 * f10 + d11 * f11) + diag;
    const float scale = -1e-4f;  // -DT
    float a00 = scale * s00 + P_MASS * c.x;
    float a01 = scale * s01 + P_MASS * c.y;
    float a10 = scale * s10 + P_MASS * c.z;
    float a11 = scale * s11 + P_MASS * c.w;

    float momx = P_MASS * vp.x - (a00 * xp.x + a01 * xp.y);
    float momy = P_MASS * vp.y - (a10 * xp.x + a11 * xp.y);

    float bxf = floorf(xp.x * INV_DX - 0.5f);
    float byf = floorf(xp.y * INV_DX - 0.5f);
    int bx = (int)bxf, by = (int)byf;
    float fxx = xp.x * INV_DX - bxf;
    float fxy = xp.y * INV_DX - byf;

    int bin = bx * N_GRID + by;
    int slot = atomicAdd(&g_cur[bin], 1);
    g_payA[slot] = make_float4(momx, momy, fxx, fxy);
    g_payB[slot] = make_float4(a00, a01, a10, a11);

    // Outputs: F at 8M, material at 12M, Jp at 13M
    ((float4*)(out + 8000000))[p] = make_float4(f00, f01, f10, f11);
    out[12000000 + p] = (float)m;
    out[13000000 + p] = jp;
}

// One warp per bin: register-accumulate 9 node partials, butterfly-reduce, store.
__global__ void __launch_bounds__(256) k_binreduce() {
    int warp = (blockIdx.x * blockDim.x + threadIdx.x) >> 5;
    int lane = threadIdx.x & 31;
    if (warp >= N_NODES) return;
    int bin = warp;
    int bx = bin >> 7, by = bin & 127;
    int start = g_off[bin];
    int n = g_cnt[bin];

    const float DX = 1.0f / 128.0f;
    const float P_MASS = 1.52587890625e-05f;
    float nx0 = (float)bx * DX, nx1 = (float)(bx + 1) * DX, nx2 = (float)(bx + 2) * DX;
    float ny0 = (float)by * DX, ny1 = (float)(by + 1) * DX, ny2 = (float)(by + 2) * DX;

    float ax[9] = {0,0,0,0,0,0,0,0,0};
    float ay[9] = {0,0,0,0,0,0,0,0,0};
    float am[9] = {0,0,0,0,0,0,0,0,0};

    for (int t = lane; t < n; t += 32) {
        float4 pa = g_payA[start + t];
        float4 pb = g_payB[start + t];
        float momx = pa.x, momy = pa.y, fxx = pa.z, fxy = pa.w;
        float a00 = pb.x, a01 = pb.y, a10 = pb.z, a11 = pb.w;
        float wx[3], wy[3];
        wx[0] = 0.5f * (1.5f - fxx) * (1.5f - fxx);
        wx[1] = 0.75f - (fxx - 1.0f) * (fxx - 1.0f);
        wx[2] = 0.5f * (fxx - 0.5f) * (fxx - 0.5f);
        wy[0] = 0.5f * (1.5f - fxy) * (1.5f - fxy);
        wy[1] = 0.75f - (fxy - 1.0f) * (fxy - 1.0f);
        wy[2] = 0.5f * (fxy - 0.5f) * (fxy - 0.5f);
        float nxs[3] = {nx0, nx1, nx2};
        float nys[3] = {ny0, ny1, ny2};
        #pragma unroll
        for (int i = 0; i < 3; i++) {
            float axx = momx + a00 * nxs[i];
            float ayx = momy + a10 * nxs[i];
            #pragma unroll
            for (int j = 0; j < 3; j++) {
                float wt = wx[i] * wy[j];
                int k = i * 3 + j;
                ax[k] += wt * (axx + a01 * nys[j]);
                ay[k] += wt * (ayx + a11 * nys[j]);
                am[k] += wt * P_MASS;
            }
        }
    }

    // butterfly reduce all 27 accumulators across the warp
    #pragma unroll
    for (int off = 16; off >= 1; off >>= 1) {
        #pragma unroll
        for (int k = 0; k < 9; k++) {
            ax[k] += __shfl_xor_sync(0xffffffff, ax[k], off);
            ay[k] += __shfl_xor_sync(0xffffffff, ay[k], off);
            am[k] += __shfl_xor_sync(0xffffffff, am[k], off);
        }
    }

    if (lane < 9) {
        #pragma unroll
        for (int k = 0; k < 9; k++) {
            if (lane == k) {
                g_pmom[k][bin] = make_float2(ax[k], ay[k]);
                g_pmass[k][bin] = am[k];
            }
        }
    }
}

__global__ void k_grid() {
    int n = blockIdx.x * blockDim.x + threadIdx.x;
    if (n >= N_NODES) return;
    int i = n >> 7;
    int j = n & 127;
    const float DT = 1e-4f;

    float vx = 0.f, vy = 0.f, mm = 0.f;
    #pragma unroll
    for (int di = 0; di < 3; di++) {
        int bi = i - di;
        if (bi < 0) continue;
        #pragma unroll
        for (int dj = 0; dj < 3; dj++) {
            int bj = j - dj;
            if (bj < 0) continue;
            int bin = bi * N_GRID + bj;
            int k = di * 3 + dj;
            float2 pm = g_pmom[k][bin];
            vx += pm.x; vy += pm.y;
            mm += g_pmass[k][bin];
        }
    }
    if (mm > 0.0f) {
        vx /= mm;
        vy /= mm;
        vy += -DT * 50.0f;
    }
    if (i < 3)    vx = fmaxf(vx, 0.0f);
    if (i >= 126) vx = fminf(vx, 0.0f);
    if (j < 3)    vy = fmaxf(vy, 0.0f);
    if (j >= 126) vy = fminf(vy, 0.0f);
    g_gv[n] = make_float2(vx, vy);
}

__global__ void __launch_bounds__(256) k_g2p(
    const float2* __restrict__ x, float* __restrict__ out)
{
    int p = blockIdx.x * blockDim.x + threadIdx.x;
    if (p >= N_PART) return;

    const float DT = 1e-4f;
    const float INV_DX = 128.0f;
    const float DX = 1.0f / 128.0f;

    float2 xp = x[p];
    float bxf = floorf(xp.x * INV_DX - 0.5f);
    float byf = floorf(xp.y * INV_DX - 0.5f);
    int bx = (int)bxf, by = (int)byf;
    float fxx = xp.x * INV_DX - bxf;
    float fxy = xp.y * INV_DX - byf;
    float wx[3], wy[3];
    wx[0] = 0.5f * (1.5f - fxx) * (1.5f - fxx);
    wx[1] = 0.75f - (fxx - 1.0f) * (fxx - 1.0f);
    wx[2] = 0.5f * (fxx - 0.5f) * (fxx - 0.5f);
    wy[0] = 0.5f * (1.5f - fxy) * (1.5f - fxy);
    wy[1] = 0.75f - (fxy - 1.0f) * (fxy - 1.0f);
    wy[2] = 0.5f * (fxy - 0.5f) * (fxy - 0.5f);

    float nvx = 0.f, nvy = 0.f;
    float b00 = 0.f, b01 = 0.f, b10 = 0.f, b11 = 0.f;

    #pragma unroll
    for (int i = 0; i < 3; i++) {
        float nodex = (float)(bx + i) * DX;
        #pragma unroll
        for (int j = 0; j < 3; j++) {
            float wt = wx[i] * wy[j];
            int idx = (bx + i) * N_GRID + (by + j);
            float2 gv = g_gv[idx];
            float nodey = (float)(by + j) * DX;
            nvx += wt * gv.x;
            nvy += wt * gv.y;
            b00 += wt * gv.x * nodex;
            b01 += wt * gv.x * nodey;
            b10 += wt * gv.y * nodex;
            b11 += wt * gv.y * nodey;
        }
    }

    const float k4 = 65536.0f;  // 4 * INV_DX^2
    float C00 = (b00 - nvx * xp.x) * k4;
    float C01 = (b01 - nvx * xp.y) * k4;
    float C10 = (b10 - nvy * xp.x) * k4;
    float C11 = (b11 - nvy * xp.y) * k4;

    ((float2*)out)[p] = make_float2(xp.x + DT * nvx, xp.y + DT * nvy);
    ((float2*)(out + 2000000))[p] = make_float2(nvx, nvy);
    ((float4*)(out + 4000000))[p] = make_float4(C00, C01, C10, C11);
}

extern "C" void kernel_launch(void* const* d_in, const int* in_sizes, int n_in,
                              void* d_out, int out_size) {
    const float2* x  = (const float2*)d_in[0];
    const float2* v  = (const float2*)d_in[1];
    const float4* C  = (const float4*)d_in[2];
    const float4* F  = (const float4*)d_in[3];
    const int* mat   = (const int*)d_in[4];
    const float* Jp  = (const float*)d_in[5];
    float* out = (float*)d_out;

    k_zero_cnt<<<(N_NODES + 255) / 256, 256>>>();
    k_count<<<(N_PART + 255) / 256, 256>>>(x);
    k_scan<<<1, 1024>>>();
    k_payload<<<(N_PART + 255) / 256, 256>>>(x, v, C, F, mat, Jp, out);
    k_binreduce<<<(N_NODES * 32 + 255) / 256, 256>>>();
    k_grid<<<(N_NODES + 255) / 256, 256>>>();
    k_g2p<<<(N_PART + 255) / 256, 256>>>(x, out);
}

// round 6
// speedup vs baseline: 1.4781x; 1.2976x over previous
#include <cuda_runtime.h>
#include <cuda_bf16.h>

#define N_PART 1000000
#define N_GRID 128
#define N_NODES (N_GRID * N_GRID)
#define NREP 8

// Grid scratch (device globals — no allocation allowed)
__device__ __align__(16) float4 g_node[NREP][N_NODES];  // (momx, momy, mass, pad)
__device__ float2 g_gv[N_NODES];   // final grid velocity for G2P

__global__ void k_zero() {
    int n = blockIdx.x * blockDim.x + threadIdx.x;
    if (n < N_NODES * NREP) {
        ((float4*)g_node)[n] = make_float4(0.f, 0.f, 0.f, 0.f);
    }
}

__global__ void __launch_bounds__(256) k_p2g(
    const float2* __restrict__ x, const float2* __restrict__ v,
    const float4* __restrict__ C, const float4* __restrict__ F,
    const int* __restrict__ material, const float* __restrict__ Jp,
    float* __restrict__ out)
{
    int p = blockIdx.x * blockDim.x + threadIdx.x;
    if (p >= N_PART) return;
    float4* __restrict__ rep = g_node[blockIdx.x & (NREP - 1)];

    const float DT = 1e-4f;
    const float INV_DX = 128.0f;
    const float DX = 1.0f / 128.0f;
    const float P_MASS = 1.52587890625e-05f;
    const float MU_0 = 1000.0f / (2.0f * 1.2f);
    const float LAM_0 = 1000.0f * 0.2f / (1.2f * 0.6f);

    float2 xp = x[p];
    float2 vp = v[p];
    float4 c = C[p];
    float4 f = F[p];
    int m = material[p];
    float jp = Jp[p];

    // F = F + DT * (C @ F)
    float f00 = f.x + DT * (c.x * f.x + c.y * f.z);
    float f01 = f.y + DT * (c.x * f.y + c.y * f.w);
    float f10 = f.z + DT * (c.z * f.x + c.w * f.z);
    float f11 = f.w + DT * (c.z * f.y + c.w * f.w);

    float h = (m == 1) ? 0.3f : expf(10.0f * (1.0f - jp));
    float mu = (m == 0) ? 0.0f : MU_0 * h;
    float lam = LAM_0 * h;

    // Singular values (algebraic): sx = Q+Rr, sy = Q-Rr
    float E  = 0.5f * (f00 + f11);
    float Fm = 0.5f * (f00 - f11);
    float G  = 0.5f * (f10 + f01);
    float H  = 0.5f * (f10 - f01);
    float q2 = E * E + H * H;
    float invQ = rsqrtf(fmaxf(q2, 1e-30f));
    float Q  = q2 * invQ;
    float Rr = sqrtf(Fm * Fm + G * G);
    float sx = Q + Rr;
    float sy = Q - Rr;

    // Polar rotation R = U Vh (trig-free): c = E/Q, s = H/Q
    float rc = E * invQ;
    float rs = H * invQ;
    float r00 = rc, r01 = -rs, r10 = rs, r11 = rc;

    // clamp & Jp update (material 2 only)
    float clx = fminf(fmaxf(sx, 0.975f), 1.0045f);
    float cly = fminf(fmaxf(sy, 0.975f), 1.0045f);
    float J;
    if (m == 2) {
        jp *= (sx * sy) / (clx * cly);
        J = clx * cly;
        // F_snow = F @ (V diag(clx/sx, cly/sy) V^T), V from eigenbasis of F^T F
        float k00 = f00 * f00 + f10 * f10;
        float k11 = f01 * f01 + f11 * f11;
        float k01 = f00 * f01 + f10 * f11;
        float d  = 0.5f * (k00 - k11);
        float rr2 = d * d + k01 * k01;
        float invr = (rr2 > 1e-24f) ? rsqrtf(rr2) : 0.0f;
        float c2 = d * invr;    // cos(2*theta)
        float s2 = k01 * invr;  // sin(2*theta)
        float rr0 = clx / sx;
        float rr1 = cly / sy;
        float avg = 0.5f * (rr0 + rr1);
        float dif = 0.5f * (rr0 - rr1);
        float m00 = avg + c2 * dif;
        float m11 = avg - c2 * dif;
        float m01 = s2 * dif;
        float nf00 = f00 * m00 + f01 * m01;
        float nf01 = f00 * m01 + f01 * m11;
        float nf10 = f10 * m00 + f11 * m01;
        float nf11 = f10 * m01 + f11 * m11;
        f00 = nf00; f01 = nf01; f10 = nf10; f11 = nf11;
    } else {
        J = sx * sy;
        if (m == 0) {
            float sj = sqrtf(J);
            f00 = sj; f01 = 0.f; f10 = 0.f; f11 = sj;
        }
    }

    // stress = -DT * (2*mu*(F-R)@F^T + I*lam*J*(J-1))   [P_VOL*4*INV_DX^2 == 1]
    float d00 = f00 - r00, d01 = f01 - r01;
    float d10 = f10 - r10, d11 = f11 - r11;
    float tm = 2.0f * mu;
    float diag = lam * J * (J - 1.0f);
    float s00 = tm * (d00 * f00 + d01 * f01) + diag;
    float s01 = tm * (d00 * f10 + d01 * f11);
    float s10 = tm * (d10 * f00 + d11 * f01);
    float s11 = tm * (d10 * f10 + d11 * f11) + diag;
    const float scale = -1e-4f;  // -DT
    float a00 = scale * s00 + P_MASS * c.x;
    float a01 = scale * s01 + P_MASS * c.y;
    float a10 = scale * s10 + P_MASS * c.z;
    float a11 = scale * s11 + P_MASS * c.w;

    float momx = P_MASS * vp.x - (a00 * xp.x + a01 * xp.y);
    float momy = P_MASS * vp.y - (a10 * xp.x + a11 * xp.y);

    float bxf = floorf(xp.x * INV_DX - 0.5f);
    float byf = floorf(xp.y * INV_DX - 0.5f);
    int bx = (int)bxf, by = (int)byf;
    float fxx = xp.x * INV_DX - bxf;
    float fxy = xp.y * INV_DX - byf;
    float wx[3], wy[3];
    wx[0] = 0.5f * (1.5f - fxx) * (1.5f - fxx);
    wx[1] = 0.75f - (fxx - 1.0f) * (fxx - 1.0f);
    wx[2] = 0.5f * (fxx - 0.5f) * (fxx - 0.5f);
    wy[0] = 0.5f * (1.5f - fxy) * (1.5f - fxy);
    wy[1] = 0.75f - (fxy - 1.0f) * (fxy - 1.0f);
    wy[2] = 0.5f * (fxy - 0.5f) * (fxy - 0.5f);

    // Fold affine into momentum: contrib = wt * (mom + A @ node_pos)
    #pragma unroll
    for (int i = 0; i < 3; i++) {
        float nodex = (float)(bx + i) * DX;
        float axx = a00 * nodex;
        float ayx = a10 * nodex;
        #pragma unroll
        for (int j = 0; j < 3; j++) {
            float nodey = (float)(by + j) * DX;
            float wt = wx[i] * wy[j];
            int idx = (bx + i) * N_GRID + (by + j);
            float cx = wt * (momx + axx + a01 * nodey);
            float cy = wt * (momy + ayx + a11 * nodey);
            atomicAdd(&rep[idx], make_float4(cx, cy, wt * P_MASS, 0.f));
        }
    }

    // Outputs: F at 8M, material at 12M, Jp at 13M
    ((float4*)(out + 8000000))[p] = make_float4(f00, f01, f10, f11);
    out[12000000 + p] = (float)m;
    out[13000000 + p] = jp;
}

__global__ void k_grid() {
    int n = blockIdx.x * blockDim.x + threadIdx.x;
    if (n >= N_NODES) return;
    int i = n >> 7;
    int j = n & 127;
    const float DT = 1e-4f;

    float vx = 0.f, vy = 0.f, mm = 0.f;
    #pragma unroll
    for (int r = 0; r < NREP; r++) {
        float4 nd = g_node[r][n];
        vx += nd.x; vy += nd.y; mm += nd.z;
    }
    if (mm > 0.0f) {
        vx /= mm;
        vy /= mm;
        vy += -DT * 50.0f;
    }
    if (i < 3)    vx = fmaxf(vx, 0.0f);
    if (i >= 126) vx = fminf(vx, 0.0f);
    if (j < 3)    vy = fmaxf(vy, 0.0f);
    if (j >= 126) vy = fminf(vy, 0.0f);
    g_gv[n] = make_float2(vx, vy);
}

__global__ void __launch_bounds__(256) k_g2p(
    const float2* __restrict__ x, float* __restrict__ out)
{
    int t = blockIdx.x * blockDim.x + threadIdx.x;
    const float DT = 1e-4f;
    const float INV_DX = 128.0f;
    const float DX = 1.0f / 128.0f;

    // two particles per thread for MLP on the grid gathers
    #pragma unroll
    for (int pp = 0; pp < 2; pp++) {
        int p = t * 2 + pp;
        if (p >= N_PART) return;

        float2 xp = x[p];
        float bxf = floorf(xp.x * INV_DX - 0.5f);
        float byf = floorf(xp.y * INV_DX - 0.5f);
        int bx = (int)bxf, by = (int)byf;
        float fxx = xp.x * INV_DX - bxf;
        float fxy = xp.y * INV_DX - byf;
        float wx[3], wy[3];
        wx[0] = 0.5f * (1.5f - fxx) * (1.5f - fxx);
        wx[1] = 0.75f - (fxx - 1.0f) * (fxx - 1.0f);
        wx[2] = 0.5f * (fxx - 0.5f) * (fxx - 0.5f);
        wy[0] = 0.5f * (1.5f - fxy) * (1.5f - fxy);
        wy[1] = 0.75f - (fxy - 1.0f) * (fxy - 1.0f);
        wy[2] = 0.5f * (fxy - 0.5f) * (fxy - 0.5f);

        float2 gv[3][3];
        #pragma unroll
        for (int i = 0; i < 3; i++)
            #pragma unroll
            for (int j = 0; j < 3; j++)
                gv[i][j] = g_gv[(bx + i) * N_GRID + (by + j)];

        float nvx = 0.f, nvy = 0.f;
        float b00 = 0.f, b01 = 0.f, b10 = 0.f, b11 = 0.f;
        #pragma unroll
        for (int i = 0; i < 3; i++) {
            float nodex = (float)(bx + i) * DX;
            #pragma unroll
            for (int j = 0; j < 3; j++) {
                float wt = wx[i] * wy[j];
                float nodey = (float)(by + j) * DX;
                float gvx = gv[i][j].x, gvy = gv[i][j].y;
                nvx += wt * gvx;
                nvy += wt * gvy;
                b00 += wt * gvx * nodex;
                b01 += wt * gvx * nodey;
                b10 += wt * gvy * nodex;
                b11 += wt * gvy * nodey;
            }
        }

        const float k4 = 65536.0f;  // 4 * INV_DX^2
        float C00 = (b00 - nvx * xp.x) * k4;
        float C01 = (b01 - nvx * xp.y) * k4;
        float C10 = (b10 - nvy * xp.x) * k4;
        float C11 = (b11 - nvy * xp.y) * k4;

        ((float2*)out)[p] = make_float2(xp.x + DT * nvx, xp.y + DT * nvy);
        ((float2*)(out + 2000000))[p] = make_float2(nvx, nvy);
        ((float4*)(out + 4000000))[p] = make_float4(C00, C01, C10, C11);
    }
}

extern "C" void kernel_launch(void* const* d_in, const int* in_sizes, int n_in,
                              void* d_out, int out_size) {
    const float2* x  = (const float2*)d_in[0];
    const float2* v  = (const float2*)d_in[1];
    const float4* C  = (const float4*)d_in[2];
    const float4* F  = (const float4*)d_in[3];
    const int* mat   = (const int*)d_in[4];
    const float* Jp  = (const float*)d_in[5];
    float* out = (float*)d_out;

    k_zero<<<(N_NODES * NREP + 255) / 256, 256>>>();
    k_p2g<<<(N_PART + 255) / 256, 256>>>(x, v, C, F, mat, Jp, out);
    k_grid<<<(N_NODES + 255) / 256, 256>>>();
    k_g2p<<<(N_PART / 2 + 255) / 256, 256>>>(x, out);
}